// round 11
// baseline (speedup 1.0000x reference)
#include <cuda_runtime.h>
#include <cuda_fp16.h>

// ---------------- problem constants ----------------
#define TT    1200
#define NF    10
#define KK    17
#define NTP   76
#define NTPG  19
#define FEAT  760
#define NSTR  240            // 5-wide strips per row
#define THREADS 256
#define Y2W   58             // Y2 row stride in floats (conflict-free)

// GEMM: D[m][n] = sum_k A[m][k] B[n][k],  m=strip(240), n=5f+j (50, pad 56), K=64
//   A cols: [0,21): x_hi[5m-8+k]  [21,42): x_lo  [42,63): x_hi again  63: 0
//   B cols: [0,21): w_hi[f][k-j]  [21,42): w_hi  [42,63): w_lo        63: 0
//   => D = x*w (error ~2^-24, fp32 accum)    [mapping verified in R8]

// ---------------- smem offsets (bytes) ----------------
#define OFF_OUT   0
#define OFF_CB    16
#define OFF_XRAW  128                 // 1216 floats (8-halo)
#define OFF_A     5120                // 240 rows x 128B, ldmatrix-swizzled
#define OFF_B     35840               // 56 rows x 128B, ldmatrix-swizzled
#define OFF_S     43008               // 10 x 240 floats
#define OFF_Y2    52608               // 240 x 58 floats
#define SMEM_TOTAL 108288

__device__ __forceinline__ void mma16816(float c[4], const unsigned a[4], const unsigned b[2]) {
    asm volatile(
        "mma.sync.aligned.m16n8k16.row.col.f32.f16.f16.f32 "
        "{%0,%1,%2,%3}, {%4,%5,%6,%7}, {%8,%9}, {%0,%1,%2,%3};"
        : "+f"(c[0]), "+f"(c[1]), "+f"(c[2]), "+f"(c[3])
        : "r"(a[0]), "r"(a[1]), "r"(a[2]), "r"(a[3]), "r"(b[0]), "r"(b[1]));
}
__device__ __forceinline__ void ldm_x4(unsigned r[4], unsigned addr) {
    asm volatile("ldmatrix.sync.aligned.m8n8.x4.shared.b16 {%0,%1,%2,%3}, [%4];"
                 : "=r"(r[0]), "=r"(r[1]), "=r"(r[2]), "=r"(r[3]) : "r"(addr));
}
__device__ __forceinline__ void ldm_x2(unsigned r[2], unsigned addr) {
    asm volatile("ldmatrix.sync.aligned.m8n8.x2.shared.b16 {%0,%1}, [%2];"
                 : "=r"(r[0]), "=r"(r[1]) : "r"(addr));
}

// A element value (half bits) for column k of strip m (xr is the 8-halo float row)
__device__ __forceinline__ unsigned short a_elem(const float* xr, int m5, int k) {
    if (k < 21) {
        return __half_as_ushort(__float2half_rn(xr[m5 + k]));
    } else if (k < 42) {
        const float t = xr[m5 + k - 21];
        const __half h = __float2half_rn(t);
        return __half_as_ushort(__float2half_rn(t - __half2float(h)));
    } else if (k < 63) {
        return __half_as_ushort(__float2half_rn(xr[m5 + k - 42]));
    }
    return 0;
}

__global__ __launch_bounds__(THREADS) void scorer_hmma2_kernel(
    const float* __restrict__ x,       // (B,1,M,T) rows of 1200
    const float* __restrict__ conv_w,  // (NF,KK)
    const float* __restrict__ conv_b,  // (NF)
    const float* __restrict__ lin_w,   // (M,FEAT)
    const float* __restrict__ lin_b,   // (M)
    float* __restrict__ out)           // (B,M,1)
{
    extern __shared__ char smem[];
    const unsigned sbase = (unsigned)__cvta_generic_to_shared(smem);
    float* s_out  = (float*)(smem + OFF_OUT);
    float* s_cb   = (float*)(smem + OFF_CB);
    float* s_xraw = (float*)(smem + OFF_XRAW);
    float* s_S    = (float*)(smem + OFF_S);
    float* s_Y2   = (float*)(smem + OFF_Y2);

    const int tid  = threadIdx.x;
    const int wid  = tid >> 5;
    const int lane = tid & 31;
    const int r    = lane >> 2;
    const int q    = lane & 3;
    const int row  = blockIdx.x;       // b*64 + m
    const int m0   = row & 63;

    // ---- Phase 0a: stage x row (halo floats), bias ----
    {
        const float* xr = x + (size_t)row * TT;
        for (int i = tid; i < TT + 16; i += THREADS) {
            const int t = i - 8;
            s_xraw[i] = (t >= 0 && t < TT) ? xr[t] : 0.f;
        }
    }
    if (tid < NF) s_cb[tid] = conv_b[tid];
    if (tid == 0) s_out[0] = 0.f;
    __syncthreads();

    // ---- Phase 0b: materialize A (240x64 halfs, swizzled) ----
    for (int idx = tid; idx < 240 * 32; idx += THREADS) {
        const int m = idx >> 5;
        const int i = idx & 31;            // u32 index: halfs 2i, 2i+1
        const int m5 = 5 * m;
        const unsigned short h0 = a_elem(s_xraw, m5, 2 * i);
        const unsigned short h1 = a_elem(s_xraw, m5, 2 * i + 1);
        const unsigned phys = (unsigned)(m * 128) + ((((i >> 2) ^ (m & 7)) << 4) + (i & 3) * 4);
        *(unsigned*)(smem + OFF_A + phys) = ((unsigned)h1 << 16) | (unsigned)h0;
    }
    // ---- Phase 0c: materialize B (56x64 halfs, swizzled) ----
    for (int idx = tid; idx < 56 * 64; idx += THREADS) {
        const int n = idx >> 6;
        const int k = idx & 63;
        unsigned short v = 0;
        if (n < 50 && k < 63) {
            const int f = n / 5, j = n - 5 * f;
            int kk; bool lo;
            if      (k < 21) { kk = k - j;      lo = false; }
            else if (k < 42) { kk = k - 21 - j; lo = false; }
            else             { kk = k - 42 - j; lo = true;  }
            if (kk >= 0 && kk < KK) {
                const float w  = conv_w[f * KK + kk];
                const __half h = __float2half_rn(w);
                v = lo ? __half_as_ushort(__float2half_rn(w - __half2float(h)))
                       : __half_as_ushort(h);
            }
        }
        const unsigned phys = (unsigned)(n * 128) + ((((k >> 3) ^ (n & 7)) << 4) + (k & 7) * 2);
        *(unsigned short*)(smem + OFF_B + phys) = v;
    }
    __syncthreads();

    // ---- Phase 1: ldmatrix-fed HMMA GEMM + fragment epilogue -> Y2 ----
    // per-lane ldmatrix row components
    const int arow_l = lane & 15;          // A: row = mt*16 + (lane&15)
    const int au_l   = lane >> 4;          // A: unit += lane>>4
    const int brow_l = lane & 7;           // B: row = nt*8 + (lane&7)
    const int bu_l   = (lane >> 3) & 1;    // B: unit += (lane>>3)&1

    #pragma unroll
    for (int mi = 0; mi < 2; ++mi) {
        const int mt = wid + 8 * mi;       // m-tile 0..14
        if (mt < 15) {
            float acc[7][4];
            #pragma unroll
            for (int nt = 0; nt < 7; ++nt)
                #pragma unroll
                for (int c = 0; c < 4; ++c) acc[nt][c] = 0.f;

            const int rowA = mt * 16 + arow_l;
            const unsigned abase = sbase + OFF_A + (unsigned)(rowA * 128);
            const unsigned asw   = (unsigned)(rowA & 7);

            #pragma unroll
            for (int ks = 0; ks < 4; ++ks) {
                unsigned a[4];
                const unsigned ua = (unsigned)(2 * ks + au_l);
                ldm_x4(a, abase + ((ua ^ asw) << 4));
                #pragma unroll
                for (int nt = 0; nt < 7; ++nt) {
                    const int rowB = nt * 8 + brow_l;
                    const unsigned ub = (unsigned)(2 * ks + bu_l);
                    unsigned b[2];
                    ldm_x2(b, sbase + OFF_B + (unsigned)(rowB * 128)
                               + ((ub ^ (unsigned)(rowB & 7)) << 4));
                    mma16816(acc[nt], a, b);
                }
            }
            // epilogue: +bias, square, store Y2
            const int mA = mt * 16 + r;
            #pragma unroll
            for (int nt = 0; nt < 7; ++nt) {
                const int n0 = 8 * nt + 2 * q;
                if (n0 < 50) {
                    const float b0 = s_cb[n0 / 5];
                    const float b1 = s_cb[(n0 + 1) / 5];
                    const float y0 = acc[nt][0] + b0, y1 = acc[nt][1] + b1;
                    const float y2 = acc[nt][2] + b0, y3 = acc[nt][3] + b1;
                    float2 v0; v0.x = y0 * y0; v0.y = y1 * y1;
                    float2 v1; v1.x = y2 * y2; v1.y = y3 * y3;
                    *(float2*)&s_Y2[(size_t)mA * Y2W + n0]       = v0;
                    *(float2*)&s_Y2[(size_t)(mA + 8) * Y2W + n0] = v1;
                }
            }
        }
    }
    __syncthreads();

    // ---- Phase 2: strip sums S[f][strip] = sum_j Y2[strip][5f+j] ----
    for (int idx = tid; idx < NF * NSTR; idx += THREADS) {
        const int f = idx / NSTR;
        const int s = idx - f * NSTR;
        const float* yp = &s_Y2[(size_t)s * Y2W + 5 * f];
        s_S[f * NSTR + s] = ((yp[0] + yp[1]) + (yp[2] + yp[3])) + yp[4];
    }
    __syncthreads();

    // ---- Phase 3: sliding pool (15 strips, hop 3) -> log -> dot ----
    float part = 0.f;
    for (int task = tid; task < NF * NTPG; task += THREADS) {   // 190 tasks
        const int f = task / NTPG;
        const int g = task - f * NTPG;
        const float* Sp = &s_S[f * NSTR + 12 * g];
        float sv[24];
        #pragma unroll
        for (int j = 0; j < 24; ++j) sv[j] = Sp[j];
        float run = 0.f;
        #pragma unroll
        for (int j = 0; j < 15; ++j) run += sv[j];
        const float4 lw = *(const float4*)&lin_w[(size_t)m0 * FEAT + f * NTP + 4 * g];
        #pragma unroll
        for (int qq = 0; qq < 4; ++qq) {
            const float p = fmaxf(run * (1.0f / 75.0f), 1e-10f);
            const float v = __logf(p);
            const float w = (qq == 0) ? lw.x : (qq == 1) ? lw.y : (qq == 2) ? lw.z : lw.w;
            part = fmaf(v, w, part);
            if (qq < 3) {
                run += (sv[15 + 3*qq] + sv[16 + 3*qq] + sv[17 + 3*qq])
                     - (sv[3*qq] + sv[1 + 3*qq] + sv[2 + 3*qq]);
            }
        }
    }
    #pragma unroll
    for (int off = 16; off > 0; off >>= 1)
        part += __shfl_down_sync(0xffffffffu, part, off);
    if (lane == 0) atomicAdd(&s_out[0], part);
    __syncthreads();

    if (tid == 0) out[row] = s_out[0] + lin_b[m0];
}

extern "C" void kernel_launch(void* const* d_in, const int* in_sizes, int n_in,
                              void* d_out, int out_size) {
    const float* x      = (const float*)d_in[0];
    const float* conv_w = (const float*)d_in[1];
    const float* conv_b = (const float*)d_in[2];
    const float* lin_w  = (const float*)d_in[3];
    const float* lin_b  = (const float*)d_in[4];
    float* out = (float*)d_out;

    cudaFuncSetAttribute(scorer_hmma2_kernel,
                         cudaFuncAttributeMaxDynamicSharedMemorySize, SMEM_TOTAL);
    scorer_hmma2_kernel<<<256 * 64, THREADS, SMEM_TOTAL>>>(x, conv_w, conv_b, lin_w, lin_b, out);
}

// round 12
// speedup vs baseline: 4.6573x; 4.6573x over previous
#include <cuda_runtime.h>

// Problem constants
#define TT    1200              // time length
#define NF    10                // conv filters
#define KK    17                // conv kernel width (pad 8 both sides)
#define NSTR  240               // 5-wide output strips per row (1200/5)
#define NTP   76                // pooled length
#define NTPG  19                // groups of 4 pooled outputs (76/4)
#define FEAT  (NF*NTP)          // 760
#define ROWS  2                 // (b,m) rows per block (the f32x2 SIMD pair)
#define THREADS 256

typedef unsigned long long u64;

__device__ __forceinline__ u64 pack2(float lo, float hi) {
    u64 r;
    asm("mov.b64 %0, {%1, %2};" : "=l"(r) : "f"(lo), "f"(hi));
    return r;
}
__device__ __forceinline__ void unpack2(u64 v, float& lo, float& hi) {
    asm("mov.b64 {%0, %1}, %2;" : "=f"(lo), "=f"(hi) : "l"(v));
}
__device__ __forceinline__ u64 ffma2(u64 a, u64 b, u64 c) {
    u64 d;
    asm("fma.rn.f32x2 %0, %1, %2, %3;" : "=l"(d) : "l"(a), "l"(b), "l"(c));
    return d;
}

__global__ __launch_bounds__(THREADS, 4) void scorer_kernel(
    const float* __restrict__ x,       // (B,1,M,T) rows of 1200
    const float* __restrict__ conv_w,  // (NF,1,KK)
    const float* __restrict__ conv_b,  // (NF)
    const float* __restrict__ lin_w,   // (M, FEAT)
    const float* __restrict__ lin_b,   // (M)
    float* __restrict__ out)           // (B,M,1)
{
    __shared__ u64 s_x2[TT + 16];                       // {row0,row1} pairs, 8-zero halo
    __shared__ __align__(16) ulonglong2 s_w4[5 * KK];   // [pair p][k]: {w2p dup, w2p+1 dup}
    __shared__ u64   s_b2[NF];                          // {b,b}
    __shared__ float s_S[ROWS][NF * NSTR];              // 5-strip sums of conv^2
    __shared__ float s_out[ROWS];

    const int tid  = threadIdx.x;
    const int row0 = blockIdx.x * ROWS;    // row = b*64 + m
    const int m0   = row0 & 63;

    // ---- Phase 0: stage paired duplicated weights, halos, interleaved x rows ----
    for (int i = tid; i < 5 * KK; i += THREADS) {
        const int p = i / KK, k = i - p * KK;
        const float wa = conv_w[(2 * p)     * KK + k];
        const float wb = conv_w[(2 * p + 1) * KK + k];
        ulonglong2 v; v.x = pack2(wa, wa); v.y = pack2(wb, wb);
        s_w4[i] = v;
    }
    if (tid < NF)   { float b = conv_b[tid]; s_b2[tid] = pack2(b, b); }
    if (tid < ROWS) s_out[tid] = 0.f;
    if (tid >= THREADS - 16) {
        int j = tid - (THREADS - 16);
        if (j < 8) s_x2[j] = 0ull;             // left halo
        else       s_x2[TT + j] = 0ull;        // right halo
    }
    {
        const float* xr0 = x + (size_t)row0 * TT;
        const float* xr1 = xr0 + TT;
        for (int t = tid; t < TT; t += THREADS)
            s_x2[8 + t] = pack2(xr0[t], xr1[t]);   // coalesced within each row
    }
    __syncthreads();

    // ---- Phase 1: per strip, filters in pairs, sliding 6-reg x window ----
    if (tid < NSTR) {
        const int s = tid;
        const u64* xp = &s_x2[5 * s];          // xp[i] = x(t = 5s - 8 + i)

        #pragma unroll 1
        for (int p = 0; p < 5; ++p) {          // filter pair (2p, 2p+1)
            const ulonglong2* wp = &s_w4[p * KK];
            const u64 ba = s_b2[2 * p];
            const u64 bb = s_b2[2 * p + 1];
            u64 a0 = ba, a1 = ba, a2 = ba, a3 = ba, a4 = ba;
            u64 d0 = bb, d1 = bb, d2 = bb, d3 = bb, d4 = bb;

            // window w0..w5 = xp[k..k+5]; load->use distance 2 taps (~40 cyc > LDS lat)
            u64 w0 = xp[0], w1 = xp[1], w2 = xp[2], w3 = xp[3], w4 = xp[4], w5 = xp[5];
            #pragma unroll
            for (int k = 0; k < KK; ++k) {
                const ulonglong2 wk = wp[k];   // one LDS.128: both filters' tap-k weight
                a0 = ffma2(w0, wk.x, a0);
                a1 = ffma2(w1, wk.x, a1);
                a2 = ffma2(w2, wk.x, a2);
                a3 = ffma2(w3, wk.x, a3);
                a4 = ffma2(w4, wk.x, a4);
                d0 = ffma2(w0, wk.y, d0);
                d1 = ffma2(w1, wk.y, d1);
                d2 = ffma2(w2, wk.y, d2);
                d3 = ffma2(w3, wk.y, d3);
                d4 = ffma2(w4, wk.y, d4);
                if (k < 15) {
                    const u64 nxt = xp[k + 6];
                    w0 = w1; w1 = w2; w2 = w3; w3 = w4; w4 = w5; w5 = nxt;
                } else if (k == 15) {
                    w0 = w1; w1 = w2; w2 = w3; w3 = w4; w4 = w5;
                }
            }
            u64 Sa = ffma2(a0, a0, 0ull);
            Sa = ffma2(a1, a1, Sa);
            Sa = ffma2(a2, a2, Sa);
            Sa = ffma2(a3, a3, Sa);
            Sa = ffma2(a4, a4, Sa);
            u64 Sb = ffma2(d0, d0, 0ull);
            Sb = ffma2(d1, d1, Sb);
            Sb = ffma2(d2, d2, Sb);
            Sb = ffma2(d3, d3, Sb);
            Sb = ffma2(d4, d4, Sb);
            float v0, v1;
            unpack2(Sa, v0, v1);
            s_S[0][(2 * p)     * NSTR + s] = v0;
            s_S[1][(2 * p)     * NSTR + s] = v1;
            unpack2(Sb, v0, v1);
            s_S[0][(2 * p + 1) * NSTR + s] = v0;
            s_S[1][(2 * p + 1) * NSTR + s] = v1;
        }
    }
    __syncthreads();

    // ---- Phase 2: sliding pool (15 strips per window, hop 3) -> log -> dot ----
    float part0 = 0.f, part1 = 0.f;
    for (int task = tid; task < ROWS * NF * NTPG; task += THREADS) {   // 380 tasks
        int r   = task / (NF * NTPG);
        int rem = task - r * (NF * NTPG);
        int f   = rem / NTPG;
        int g   = rem - f * NTPG;              // covers tp = 4g .. 4g+3

        const float* Sp = &s_S[r][f * NSTR + 12 * g];
        float sv[24];
        #pragma unroll
        for (int j = 0; j < 24; ++j) sv[j] = Sp[j];

        float run = 0.f;
        #pragma unroll
        for (int j = 0; j < 15; ++j) run += sv[j];

        const float4 lw = *(const float4*)&lin_w[(size_t)(m0 + r) * FEAT + f * NTP + 4 * g];
        float acc = 0.f;
        #pragma unroll
        for (int q = 0; q < 4; ++q) {
            float pp = fmaxf(run * (1.0f / 75.0f), 1e-10f);
            float v = __logf(pp);
            float w = (q == 0) ? lw.x : (q == 1) ? lw.y : (q == 2) ? lw.z : lw.w;
            acc = fmaf(v, w, acc);
            if (q < 3) {
                run += (sv[15 + 3*q] + sv[16 + 3*q] + sv[17 + 3*q])
                     - (sv[3*q] + sv[1 + 3*q] + sv[2 + 3*q]);
            }
        }
        if (r == 0) part0 += acc; else part1 += acc;
    }
    #pragma unroll
    for (int off = 16; off > 0; off >>= 1) {
        part0 += __shfl_down_sync(0xffffffffu, part0, off);
        part1 += __shfl_down_sync(0xffffffffu, part1, off);
    }
    if ((tid & 31) == 0) {
        atomicAdd(&s_out[0], part0);
        atomicAdd(&s_out[1], part1);
    }
    __syncthreads();

    if (tid < ROWS) out[row0 + tid] = s_out[tid] + lin_b[m0 + tid];
}

extern "C" void kernel_launch(void* const* d_in, const int* in_sizes, int n_in,
                              void* d_out, int out_size) {
    const float* x      = (const float*)d_in[0];
    const float* conv_w = (const float*)d_in[1];
    const float* conv_b = (const float*)d_in[2];
    const float* lin_w  = (const float*)d_in[3];
    const float* lin_b  = (const float*)d_in[4];
    float* out = (float*)d_out;

    const int n_rows = 256 * 64;               // B*M
    scorer_kernel<<<n_rows / ROWS, THREADS>>>(x, conv_w, conv_b, lin_w, lin_b, out);
}